// round 8
// baseline (speedup 1.0000x reference)
#include <cuda_runtime.h>

#define Hh 96
#define Ww 96
#define TPB 384   // 8 h-groups (x12 rows) * 48 w-groups (x2 cols, f32x2)
#define TH  12    // h-rows per thread

typedef unsigned long long u64;

__device__ __forceinline__ u64 ffma2(u64 a, u64 b, u64 c) {
    u64 d;
    asm("fma.rn.f32x2 %0, %1, %2, %3;" : "=l"(d) : "l"(a), "l"(b), "l"(c));
    return d;
}

__global__ __launch_bounds__(TPB, 2) void conv_h_kernel(
    const float* __restrict__ x, const float* __restrict__ pe,
    const float* __restrict__ wt, const float* __restrict__ bias,
    const float* __restrict__ rw, float* __restrict__ out, int C)
{
    __shared__ __align__(16) float xs[Hh][Ww];     // 36 KB input tile (pe added)
    __shared__ __align__(16) float2 wrvA[194];     // logical idx i in [-1,192] at wrvA[i+1], splatted

    const int bc = blockIdx.x;        // b*C + c
    const int c  = bc % C;
    const int t  = threadIdx.x;

    const float* xp  = x + (size_t)bc * (Hh * Ww);
    const float* pep = pe + c * Hh;

    // Load tile, fusing positional-embedding add. 2304 float4s / 384 thr = 6 iters.
    #pragma unroll
    for (int i = t; i < (Hh * Ww) / 4; i += TPB) {
        float4 v = ((const float4*)xp)[i];
        float p = pep[i / 24];   // all 4 elems of a float4 are in row i/24
        v.x += p; v.y += p; v.z += p; v.w += p;
        ((float4*)&xs[0][0])[i] = v;
    }

    // Combined weight wc[k] = wt[c,k] + (k<3 ? rw[c,k] : 0).
    // A(i) := wc[(191 - i) mod 96], stored splatted at wrvA[i+1], i = -1..192.
    if (t < 194) {
        int idx = (192 - t) % Hh;          // (191 - (t-1)) mod 96
        float wv = wt[c * Hh + idx];
        if (idx < 3) wv += rw[c * 3 + idx];
        wrvA[t] = make_float2(wv, wv);
    }
    __syncthreads();

    const int ty = t / 48, wx = t % 48;    // h0 = ty*12, w-pair = wx
    const int h0 = ty * TH;

    const u64* wA = (const u64*)wrvA + 1;  // logical index (valid for i in [-1,192])

    const float bv = bias[c];
    u64 binit;
    asm("mov.b64 %0, {%1, %1};" : "=l"(binit) : "f"(bv));

    u64 acc[TH];
    #pragma unroll
    for (int r = 0; r < TH; r++) acc[r] = binit;

    // Weight ring: at iteration jj, weight(r) = A(95-jj+h0+r) lives in ring[(r-jj) mod 12].
    u64 ring[TH];
    #pragma unroll
    for (int i = 0; i < TH; i++) ring[i] = wA[95 + h0 + i];

    const u64* xcol = (const u64*)&xs[0][0] + wx;   // f32x2 column, row stride 48

    u64 xv = xcol[0];
    // out[h0+r][2wx..2wx+1] = bias + sum_jj A(95-jj+h0+r) * xs[jj][2wx..]
    // Outer loop NOT unrolled (8 iters); inner 12 fully unrolled -> jj%12 == js is
    // compile-time, so all ring indices are register renames. Body ~1.5KB, fits L0 I$.
    for (int jb = 0; jb < Hh / TH; jb++) {
        int jj0 = jb * TH;
        #pragma unroll
        for (int js = 0; js < TH; js++) {
            const int jj = jj0 + js;       // jj % 12 == js (compile-time)
            u64 xn = (jj < Hh - 1) ? xcol[(jj + 1) * 48] : 0ULL;
            u64 wn = wA[94 - jj + h0];     // weight(0) for iteration jj+1; wA[-1..] valid
            #pragma unroll
            for (int r = 0; r < TH; r++)
                acc[r] = ffma2(ring[(r + TH - js) % TH], xv, acc[r]);
            ring[(TH - 1 - js)] = wn;      // slot (11 - jj) mod 12 == 11 - js
            xv = xn;
        }
    }

    float* op = out + (size_t)bc * (Hh * Ww) + wx * 2;
    #pragma unroll
    for (int r = 0; r < TH; r++) {
        union { u64 u; float2 f; } a; a.u = acc[r];
        *(float2*)&op[(h0 + r) * Ww] = a.f;
    }
}

extern "C" void kernel_launch(void* const* d_in, const int* in_sizes, int n_in,
                              void* d_out, int out_size) {
    const float* x    = (const float*)d_in[0];
    const float* pe   = (const float*)d_in[1];
    const float* wt   = (const float*)d_in[2];
    const float* bias = (const float*)d_in[3];
    const float* rw   = (const float*)d_in[4];
    float* out = (float*)d_out;

    const int nblocks = in_sizes[0] / (Hh * Ww);  // B*C = 4096
    const int C       = in_sizes[2] / Hh;         // 256

    conv_h_kernel<<<nblocks, TPB>>>(x, pe, wt, bias, rw, out, C);
}

// round 10
// speedup vs baseline: 2.4111x; 2.4111x over previous
#include <cuda_runtime.h>
#include <cuda_fp16.h>

#define Hh 96
#define Ww 96
#define TPB 384      // 12 warps: 6 M-strips x 2 N-strips
#define PAD 104      // halfs per smem row (208B stride: conflict-free ldmatrix)

typedef unsigned int u32;

static __device__ __forceinline__ u32 smem_u32(const void* p) {
    u32 a;
    asm("{ .reg .u64 t; cvta.to.shared.u64 t, %1; cvt.u32.u64 %0, t; }" : "=r"(a) : "l"(p));
    return a;
}

__global__ __launch_bounds__(TPB, 2) void conv_mma_kernel(
    const float* __restrict__ x, const float* __restrict__ pe,
    const float* __restrict__ wt, const float* __restrict__ bias,
    const float* __restrict__ rw, float* __restrict__ out, int C)
{
    __shared__ __align__(16) __half As[Hh * PAD];   // circulant weights, M x K row-major
    __shared__ __align__(16) __half Bs[Hh * PAD];   // x + pe, K x N row-major
    __shared__ __half wcd[192];                     // doubled combined weights

    const int t  = threadIdx.x;
    const int bc = blockIdx.x;          // b*C + c
    const int c  = bc % C;

    const float* xp  = x + (size_t)bc * (Hh * Ww);
    const float* pep = pe + c * Hh;

    // combined weight wc[k] = wt[c,k] + (k<3 ? rw[c,k] : 0), doubled for mod-free index
    if (t < 96) {
        float w = wt[c * Hh + t] + (t < 3 ? rw[c * 3 + t] : 0.0f);
        __half hv = __float2half_rn(w);
        wcd[t] = hv; wcd[t + 96] = hv;
    }

    // B fill: Bs[k][n] = fp16(x[k][n] + pe[k]),  K x N row-major, PAD stride
    #pragma unroll
    for (int i = t; i < (Hh * Ww) / 4; i += TPB) {
        float4 v = ((const float4*)xp)[i];
        int k = i / 24, n0 = (i % 24) * 4;
        float p = pep[k];
        __half2 h01 = __floats2half2_rn(v.x + p, v.y + p);
        __half2 h23 = __floats2half2_rn(v.z + p, v.w + p);
        *(uint2*)&Bs[k * PAD + n0] = make_uint2(*(u32*)&h01, *(u32*)&h23);
    }
    __syncthreads();

    // A fill: As[h][j] = wc[(j-h) mod 96] = wcd[j-h+96]  (j-h+96 in [1,191])
    #pragma unroll
    for (int i = t; i < (Hh * Ww) / 4; i += TPB) {
        int h = i / 24, j0 = (i % 24) * 4;
        int idx = j0 - h + 96;
        u32 u01 = *(unsigned short*)&wcd[idx]     | ((u32)*(unsigned short*)&wcd[idx + 1] << 16);
        u32 u23 = *(unsigned short*)&wcd[idx + 2] | ((u32)*(unsigned short*)&wcd[idx + 3] << 16);
        *(uint2*)&As[h * PAD + j0] = make_uint2(u01, u23);
    }
    __syncthreads();

    // warp tiling: 16(M) x 48(N) per warp
    const int wid = t >> 5, lane = t & 31;
    const int mrow = (wid >> 1) * 16;
    const int ncol = (wid & 1) * 48;
    const int lr = lane & 15, lc = lane >> 4;

    const u32 sA = smem_u32(As), sB = smem_u32(Bs);
    const float bv = bias[c];

    float acc[6][4];
    #pragma unroll
    for (int n = 0; n < 6; n++)
        #pragma unroll
        for (int q = 0; q < 4; q++) acc[n][q] = bv;   // bias folded into accumulator init

    #pragma unroll
    for (int k6 = 0; k6 < 6; k6++) {
        u32 a0, a1, a2, a3;
        u32 aaddr = sA + (u32)((mrow + lr) * PAD + k6 * 16 + lc * 8) * 2;
        asm volatile("ldmatrix.sync.aligned.m8n8.x4.shared.b16 {%0,%1,%2,%3}, [%4];"
                     : "=r"(a0), "=r"(a1), "=r"(a2), "=r"(a3) : "r"(aaddr));
        #pragma unroll
        for (int n = 0; n < 6; n++) {
            u32 b0, b1;
            u32 baddr = sB + (u32)((k6 * 16 + lr) * PAD + ncol + n * 8) * 2;
            asm volatile("ldmatrix.sync.aligned.m8n8.x2.trans.shared.b16 {%0,%1}, [%2];"
                         : "=r"(b0), "=r"(b1) : "r"(baddr));
            asm volatile(
                "mma.sync.aligned.m16n8k16.row.col.f32.f16.f16.f32 "
                "{%0,%1,%2,%3}, {%4,%5,%6,%7}, {%8,%9}, {%0,%1,%2,%3};"
                : "+f"(acc[n][0]), "+f"(acc[n][1]), "+f"(acc[n][2]), "+f"(acc[n][3])
                : "r"(a0), "r"(a1), "r"(a2), "r"(a3), "r"(b0), "r"(b1));
        }
    }

    // epilogue: d-fragment rows lane/4 and lane/4+8, cols (lane%4)*2
    float* op = out + (size_t)bc * (Hh * Ww);
    const int row  = mrow + (lane >> 2);
    const int col0 = ncol + (lane & 3) * 2;
    #pragma unroll
    for (int n = 0; n < 6; n++) {
        *(float2*)&op[row * Ww + col0 + n * 8]       = make_float2(acc[n][0], acc[n][1]);
        *(float2*)&op[(row + 8) * Ww + col0 + n * 8] = make_float2(acc[n][2], acc[n][3]);
    }
}

extern "C" void kernel_launch(void* const* d_in, const int* in_sizes, int n_in,
                              void* d_out, int out_size) {
    const float* x    = (const float*)d_in[0];
    const float* pe   = (const float*)d_in[1];
    const float* wt   = (const float*)d_in[2];
    const float* bias = (const float*)d_in[3];
    const float* rw   = (const float*)d_in[4];
    float* out = (float*)d_out;

    const int nblocks = in_sizes[0] / (Hh * Ww);  // B*C = 4096
    const int C       = in_sizes[2] / Hh;         // 256

    conv_mma_kernel<<<nblocks, TPB>>>(x, pe, wt, bias, rw, out, C);
}

// round 11
// speedup vs baseline: 2.6406x; 1.0952x over previous
#include <cuda_runtime.h>
#include <cuda_fp16.h>

#define Hh 96
#define Ww 96
#define TPB 384      // 12 warps: 3 M-strips (x32 rows) x 4 N-strips (x24 cols)
#define PAD 104      // halfs per smem row (208B stride: conflict-free ldmatrix)

typedef unsigned int u32;

static __device__ __forceinline__ u32 smem_u32(const void* p) {
    u32 a;
    asm("{ .reg .u64 t; cvta.to.shared.u64 t, %1; cvt.u32.u64 %0, t; }" : "=r"(a) : "l"(p));
    return a;
}

__global__ __launch_bounds__(TPB, 3) void conv_mma_kernel(
    const float* __restrict__ x, const float* __restrict__ pe,
    const float* __restrict__ wt, const float* __restrict__ bias,
    const float* __restrict__ rw, float* __restrict__ out, int C)
{
    __shared__ __align__(16) __half As[Hh * PAD];   // circulant weights, M x K row-major
    __shared__ __align__(16) __half Bs[Hh * PAD];   // x + pe, K x N row-major
    __shared__ __half wcd[192];                     // doubled combined weights

    const int t  = threadIdx.x;
    const int bc = blockIdx.x;          // b*C + c
    const int c  = bc % C;

    const float* xp  = x + (size_t)bc * (Hh * Ww);
    const float* pep = pe + c * Hh;

    // combined weight wc[k] = wt[c,k] + (k<3 ? rw[c,k] : 0), doubled for mod-free index
    if (t < 96) {
        float w = wt[c * Hh + t] + (t < 3 ? rw[c * 3 + t] : 0.0f);
        __half hv = __float2half_rn(w);
        wcd[t] = hv; wcd[t + 96] = hv;
    }

    // B fill: Bs[k][n] = fp16(x[k][n] + pe[k]),  K x N row-major, PAD stride
    #pragma unroll
    for (int i = t; i < (Hh * Ww) / 4; i += TPB) {
        float4 v = ((const float4*)xp)[i];
        int k = i / 24, n0 = (i % 24) * 4;
        float p = pep[k];
        __half2 h01 = __floats2half2_rn(v.x + p, v.y + p);
        __half2 h23 = __floats2half2_rn(v.z + p, v.w + p);
        *(uint2*)&Bs[k * PAD + n0] = make_uint2(*(u32*)&h01, *(u32*)&h23);
    }
    __syncthreads();

    // A fill: As[h][j] = wc[(j-h) mod 96] = wcd[j-h+96]  (j-h+96 in [1,191])
    #pragma unroll
    for (int i = t; i < (Hh * Ww) / 4; i += TPB) {
        int h = i / 24, j0 = (i % 24) * 4;
        int idx = j0 - h + 96;
        u32 u01 = *(unsigned short*)&wcd[idx]     | ((u32)*(unsigned short*)&wcd[idx + 1] << 16);
        u32 u23 = *(unsigned short*)&wcd[idx + 2] | ((u32)*(unsigned short*)&wcd[idx + 3] << 16);
        *(uint2*)&As[h * PAD + j0] = make_uint2(u01, u23);
    }
    __syncthreads();

    // warp tiling: 32(M) x 24(N) per warp; B-frag shared by both m16-frags
    const int wid = t >> 5, lane = t & 31;
    const int mrow = (wid >> 2) * 32;       // 3 M-strips
    const int ncol = (wid & 3) * 24;        // 4 N-strips
    const int lr = lane & 15, lc = lane >> 4;

    const u32 sA = smem_u32(As), sB = smem_u32(Bs);
    const float bv = bias[c];

    float acc[2][3][4];
    #pragma unroll
    for (int mf = 0; mf < 2; mf++)
        #pragma unroll
        for (int n = 0; n < 3; n++)
            #pragma unroll
            for (int q = 0; q < 4; q++) acc[mf][n][q] = bv;   // bias in acc init

    #pragma unroll
    for (int k6 = 0; k6 < 6; k6++) {
        u32 a[2][4];
        #pragma unroll
        for (int mf = 0; mf < 2; mf++) {
            u32 aaddr = sA + (u32)((mrow + mf * 16 + lr) * PAD + k6 * 16 + lc * 8) * 2;
            asm volatile("ldmatrix.sync.aligned.m8n8.x4.shared.b16 {%0,%1,%2,%3}, [%4];"
                         : "=r"(a[mf][0]), "=r"(a[mf][1]), "=r"(a[mf][2]), "=r"(a[mf][3])
                         : "r"(aaddr));
        }
        #pragma unroll
        for (int n = 0; n < 3; n++) {
            u32 b0, b1;
            u32 baddr = sB + (u32)((k6 * 16 + lr) * PAD + ncol + n * 8) * 2;
            asm volatile("ldmatrix.sync.aligned.m8n8.x2.trans.shared.b16 {%0,%1}, [%2];"
                         : "=r"(b0), "=r"(b1) : "r"(baddr));
            #pragma unroll
            for (int mf = 0; mf < 2; mf++)
                asm volatile(
                    "mma.sync.aligned.m16n8k16.row.col.f32.f16.f16.f32 "
                    "{%0,%1,%2,%3}, {%4,%5,%6,%7}, {%8,%9}, {%0,%1,%2,%3};"
                    : "+f"(acc[mf][n][0]), "+f"(acc[mf][n][1]),
                      "+f"(acc[mf][n][2]), "+f"(acc[mf][n][3])
                    : "r"(a[mf][0]), "r"(a[mf][1]), "r"(a[mf][2]), "r"(a[mf][3]),
                      "r"(b0), "r"(b1));
        }
    }

    // epilogue: per m-frag, rows lane/4 and lane/4+8, cols (lane%4)*2
    float* op = out + (size_t)bc * (Hh * Ww);
    const int rbase = mrow + (lane >> 2);
    const int col0  = ncol + (lane & 3) * 2;
    #pragma unroll
    for (int mf = 0; mf < 2; mf++) {
        const int row = rbase + mf * 16;
        #pragma unroll
        for (int n = 0; n < 3; n++) {
            *(float2*)&op[row * Ww + col0 + n * 8]       = make_float2(acc[mf][n][0], acc[mf][n][1]);
            *(float2*)&op[(row + 8) * Ww + col0 + n * 8] = make_float2(acc[mf][n][2], acc[mf][n][3]);
        }
    }
}

extern "C" void kernel_launch(void* const* d_in, const int* in_sizes, int n_in,
                              void* d_out, int out_size) {
    const float* x    = (const float*)d_in[0];
    const float* pe   = (const float*)d_in[1];
    const float* wt   = (const float*)d_in[2];
    const float* bias = (const float*)d_in[3];
    const float* rw   = (const float*)d_in[4];
    float* out = (float*)d_out;

    const int nblocks = in_sizes[0] / (Hh * Ww);  // B*C = 4096
    const int C       = in_sizes[2] / Hh;         // 256

    conv_mma_kernel<<<nblocks, TPB>>>(x, pe, wt, bias, rw, out, C);
}